// round 1
// baseline (speedup 1.0000x reference)
#include <cuda_runtime.h>

#define NN      262144          // 64^3
#define NNZ_TOT (7 * NN)
#define BS      128
#define RBLOCKS 592

// Scratch (static device globals — allocation-free rule)
__device__ float  g_ypT[(size_t)NN * BS];   // y_pred transposed (N, BS)
__device__ float  g_ytT[(size_t)NN * BS];   // y_true transposed (N, BS)
__device__ float  g_yhT[(size_t)NN * BS];   // Yhat transposed  (N, BS)
__device__ double g_s1[BS], g_s3[BS];
__device__ double g_part[(size_t)RBLOCKS * 3 * BS];

// ---------------------------------------------------------------- zero Yhat
__global__ void zero_kernel() {
    size_t i = (size_t)blockIdx.x * blockDim.x + threadIdx.x;
    size_t total = (size_t)NN * BS / 4;
    float4* p = (float4*)g_yhT;
    if (i < total) p[i] = make_float4(0.f, 0.f, 0.f, 0.f);
}

// ------------------------------------------------- transpose (BS,N)->(N,BS)
__global__ void transpose_kernel(const float* __restrict__ yp,
                                 const float* __restrict__ yt) {
    __shared__ float tp[32][33];
    __shared__ float tt[32][33];
    int n0 = blockIdx.x * 32;
    int b0 = blockIdx.y * 32;
    int tx = threadIdx.x, ty = threadIdx.y;   // block (32,8)
#pragma unroll
    for (int r = 0; r < 32; r += 8) {
        size_t src = (size_t)(b0 + ty + r) * NN + n0 + tx;
        tp[ty + r][tx] = yp[src];
        tt[ty + r][tx] = yt[src];
    }
    __syncthreads();
#pragma unroll
    for (int r = 0; r < 32; r += 8) {
        size_t dst = (size_t)(n0 + ty + r) * BS + b0 + tx;
        g_ypT[dst] = tp[tx][ty + r];
        g_ytT[dst] = tt[tx][ty + r];
    }
}

// ----------------------------------------------- s1 = yt.yp, s3 = yt.yt
__global__ void dots_kernel(const float* __restrict__ yp,
                            const float* __restrict__ yt) {
    int b = blockIdx.x;
    const float4* p4 = (const float4*)(yp + (size_t)b * NN);
    const float4* t4 = (const float4*)(yt + (size_t)b * NN);
    float s1 = 0.f, s3 = 0.f;
    for (int i = threadIdx.x; i < NN / 4; i += blockDim.x) {
        float4 p = p4[i], t = t4[i];
        s1 += t.x * p.x + t.y * p.y + t.z * p.z + t.w * p.w;
        s3 += t.x * t.x + t.y * t.y + t.z * t.z + t.w * t.w;
    }
    __shared__ double sh1[256];
    __shared__ double sh3[256];
    sh1[threadIdx.x] = (double)s1;
    sh3[threadIdx.x] = (double)s3;
    __syncthreads();
    for (int s = 128; s > 0; s >>= 1) {
        if (threadIdx.x < s) {
            sh1[threadIdx.x] += sh1[threadIdx.x + s];
            sh3[threadIdx.x] += sh3[threadIdx.x + s];
        }
        __syncthreads();
    }
    if (threadIdx.x == 0) { g_s1[b] = sh1[0]; g_s3[b] = sh3[0]; }
}

// -------------------------------------- scatter: Yhat[:,r] += v * yp[:,c]
__global__ void scatter_kernel(const float* __restrict__ vals,
                               const int* __restrict__ rows,
                               const int* __restrict__ cols) {
    int lane = threadIdx.x & 31;
    int gw   = (blockIdx.x * blockDim.x + threadIdx.x) >> 5;
    int nw   = (gridDim.x * blockDim.x) >> 5;
    const float4* yp4 = (const float4*)g_ypT;
    float4*       yh4 = (float4*)g_yhT;
    for (int i = gw; i < NNZ_TOT; i += nw) {
        int   r = __ldg(rows + i);
        int   c = __ldg(cols + i);
        float v = __ldg(vals + i);
        float4 p = yp4[(size_t)c * 32 + lane];
        float4 q = make_float4(v * p.x, v * p.y, v * p.z, v * p.w);
        atomicAdd(&yh4[(size_t)r * 32 + lane], q);   // RED.v4 on sm_90+
    }
}

// -------------------------- s2 = yp.Yhat, s4 = yt.Yhat, s5 = Yhat.Yhat
__global__ void reduce_kernel() {
    int tid  = threadIdx.x;          // 256 threads = 8 warps
    int lane = tid & 31;
    int wid  = tid >> 5;
    int gw   = blockIdx.x * 8 + wid;
    int nw   = gridDim.x * 8;
    const float4* yp4 = (const float4*)g_ypT;
    const float4* yt4 = (const float4*)g_ytT;
    const float4* yh4 = (const float4*)g_yhT;
    float4 a2 = make_float4(0, 0, 0, 0);
    float4 a4 = make_float4(0, 0, 0, 0);
    float4 a5 = make_float4(0, 0, 0, 0);
    for (int n = gw; n < NN; n += nw) {
        size_t base = (size_t)n * 32 + lane;
        float4 p = yp4[base], t = yt4[base], h = yh4[base];
        a2.x += p.x * h.x; a2.y += p.y * h.y; a2.z += p.z * h.z; a2.w += p.w * h.w;
        a4.x += t.x * h.x; a4.y += t.y * h.y; a4.z += t.z * h.z; a4.w += t.w * h.w;
        a5.x += h.x * h.x; a5.y += h.y * h.y; a5.z += h.z * h.z; a5.w += h.w * h.w;
    }
    __shared__ float sh[3][8][128];
    int bidx = lane * 4;
    sh[0][wid][bidx + 0] = a2.x; sh[0][wid][bidx + 1] = a2.y;
    sh[0][wid][bidx + 2] = a2.z; sh[0][wid][bidx + 3] = a2.w;
    sh[1][wid][bidx + 0] = a4.x; sh[1][wid][bidx + 1] = a4.y;
    sh[1][wid][bidx + 2] = a4.z; sh[1][wid][bidx + 3] = a4.w;
    sh[2][wid][bidx + 0] = a5.x; sh[2][wid][bidx + 1] = a5.y;
    sh[2][wid][bidx + 2] = a5.z; sh[2][wid][bidx + 3] = a5.w;
    __syncthreads();
    if (tid < 128) {
        double d2 = 0, d4 = 0, d5 = 0;
#pragma unroll
        for (int w = 0; w < 8; w++) {
            d2 += (double)sh[0][w][tid];
            d4 += (double)sh[1][w][tid];
            d5 += (double)sh[2][w][tid];
        }
        size_t o = (size_t)blockIdx.x * 3 * BS;
        g_part[o + tid]       = d2;
        g_part[o + 128 + tid] = d4;
        g_part[o + 256 + tid] = d5;
    }
}

// ------------------------------------------------------------ final scalar
__global__ void final_kernel(float* out) {
    int b = threadIdx.x;             // 128 threads
    double s2 = 0, s4 = 0, s5 = 0;
    for (int blk = 0; blk < RBLOCKS; blk++) {
        size_t o = (size_t)blk * 3 * BS;
        s2 += g_part[o + b];
        s4 += g_part[o + 128 + b];
        s5 += g_part[o + 256 + b];
    }
    double scale = g_s1[b] / s2;
    double r = g_s3[b] - 2.0 * scale * s4 + scale * scale * s5;
    __shared__ double sh[128];
    sh[b] = r;
    __syncthreads();
    for (int s = 64; s > 0; s >>= 1) {
        if (b < s) sh[b] += sh[b + s];
        __syncthreads();
    }
    if (b == 0) out[0] = (float)(sh[0] / (double)BS);
}

extern "C" void kernel_launch(void* const* d_in, const int* in_sizes, int n_in,
                              void* d_out, int out_size) {
    const float* yp   = (const float*)d_in[0];
    const float* yt   = (const float*)d_in[1];
    const float* vals = (const float*)d_in[2];
    const int*   rows = (const int*)d_in[3];
    const int*   cols = (const int*)d_in[4];
    float*       out  = (float*)d_out;

    size_t total4 = (size_t)NN * BS / 4;
    zero_kernel<<<(unsigned)((total4 + 1023) / 1024), 1024>>>();
    dim3 tg(NN / 32, BS / 32);
    transpose_kernel<<<tg, dim3(32, 8)>>>(yp, yt);
    dots_kernel<<<BS, 256>>>(yp, yt);
    scatter_kernel<<<2048, 256>>>(vals, rows, cols);
    reduce_kernel<<<RBLOCKS, 256>>>();
    final_kernel<<<1, 128>>>(out);
}

// round 2
// speedup vs baseline: 1.9146x; 1.9146x over previous
#include <cuda_runtime.h>

#define NN      262144          // 64^3
#define NNZ_TOT (7 * NN)
#define BS      128
#define CH      32              // batch chunk width
#define NCHUNK  (BS / CH)       // 4

// Scratch (allocation-free rule): per-chunk transposed buffers, 32 MB each
__device__ float  g_ypT[(size_t)NN * CH];   // y_pred chunk, (N, 32)
__device__ float  g_yhT[(size_t)NN * CH];   // Yhat  chunk, (N, 32)
__device__ double g_acc[5 * BS];            // s1..s5 per batch element

// ------------------------------------------------------------- zero g_acc
__global__ void zero_acc_kernel() {
    g_acc[threadIdx.x] = 0.0;   // 640 threads
}

// ---------------- per-chunk prep: transpose yp chunk + zero yh chunk
// grid = N/32 blocks, block = (32, 8)
__global__ void prep_chunk(const float* __restrict__ yp, int b0) {
    __shared__ float tp[32][33];
    int n0 = blockIdx.x * 32;
    int tx = threadIdx.x, ty = threadIdx.y;
#pragma unroll
    for (int r = 0; r < 32; r += 8)
        tp[ty + r][tx] = yp[(size_t)(b0 + ty + r) * NN + n0 + tx];

    // zero the Yhat chunk rows handled by this block (32 n * 32 b = 256 float4)
    int tid = ty * 32 + tx;
    ((float4*)g_yhT)[(size_t)n0 * 8 + tid] = make_float4(0.f, 0.f, 0.f, 0.f);

    __syncthreads();
#pragma unroll
    for (int r = 0; r < 32; r += 8)
        g_ypT[(size_t)(n0 + ty + r) * 32 + tx] = tp[tx][ty + r];
}

// ---------------- per-chunk scatter: Yhat_c[:, r] += v * yp_c[:, c]
// 8 threads (2 x float4) per nnz; ypT/yhT rows are single 128B lines.
__global__ void scatter_chunk(const float* __restrict__ vals,
                              const int* __restrict__ rows,
                              const int* __restrict__ cols) {
    const float4* yp4 = (const float4*)g_ypT;
    float4*       yh4 = (float4*)g_yhT;
    int gid    = blockIdx.x * blockDim.x + threadIdx.x;
    int stride = gridDim.x * blockDim.x;
    int sub    = gid & 7;
    for (int q = gid >> 3; q < NNZ_TOT; q += (stride >> 3)) {
        int   r = __ldg(rows + q);
        int   c = __ldg(cols + q);
        float v = __ldg(vals + q);
        float4 p = __ldg(&yp4[(size_t)c * 8 + sub]);
        atomicAdd(&yh4[(size_t)r * 8 + sub],
                  make_float4(v * p.x, v * p.y, v * p.z, v * p.w));
    }
}

// ---------------- per-chunk fused reduce: s1..s5 for batch rows [b0, b0+32)
// Tile-transposes y_true on the fly in smem; ypT/yhT chunk read from L2.
// grid = N/256 blocks, block = 256
__global__ void reduce_chunk(const float* __restrict__ yt, int b0) {
    __shared__ float sm[32][257];
    __shared__ float red[5][8][32];
    int tid = threadIdx.x;
    int n0  = blockIdx.x * 256;

    // load y_true tile (32 b x 256 n), coalesced float4
    for (int idx = tid; idx < 2048; idx += 256) {
        int row = idx >> 6;         // 0..31 (batch within chunk)
        int c4  = idx & 63;         // 0..63 (float4 within 256 n)
        float4 v = __ldg((const float4*)(yt + (size_t)(b0 + row) * NN + n0 + c4 * 4));
        sm[row][c4 * 4 + 0] = v.x;
        sm[row][c4 * 4 + 1] = v.y;
        sm[row][c4 * 4 + 2] = v.z;
        sm[row][c4 * 4 + 3] = v.w;
    }
    __syncthreads();

    int w = tid >> 5;               // warp 0..7 -> n sub-range
    int j = tid & 31;               // lane = batch index within chunk
    int nl0 = w * 32;
    float a1 = 0.f, a2 = 0.f, a3 = 0.f, a4 = 0.f, a5 = 0.f;
#pragma unroll 4
    for (int i = 0; i < 32; i++) {
        size_t n = (size_t)(n0 + nl0 + i);
        float p = g_ypT[n * 32 + j];
        float h = g_yhT[n * 32 + j];
        float t = sm[j][nl0 + i];
        a1 += t * p;
        a2 += p * h;
        a3 += t * t;
        a4 += t * h;
        a5 += h * h;
    }

    // Dead data: each 128B line (one n) was read only by this warp.
    // Discard to avoid dirty-line writeback to DRAM. Buffers are fully
    // rewritten (prep_chunk) before any future read.
    {
        size_t n = (size_t)(n0 + nl0 + j);
        asm volatile("discard.global.L2 [%0], 128;" :: "l"(&g_ypT[n * 32]));
        asm volatile("discard.global.L2 [%0], 128;" :: "l"(&g_yhT[n * 32]));
    }

    red[0][w][j] = a1;
    red[1][w][j] = a2;
    red[2][w][j] = a3;
    red[3][w][j] = a4;
    red[4][w][j] = a5;
    __syncthreads();

    if (tid < 160) {
        int acc = tid >> 5;         // 0..4
        int jj  = tid & 31;
        float s = 0.f;
#pragma unroll
        for (int ww = 0; ww < 8; ww++) s += red[acc][ww][jj];
        atomicAdd(&g_acc[acc * BS + b0 + jj], (double)s);
    }
}

// ------------------------------------------------------------ final scalar
__global__ void final_kernel(float* out) {
    int b = threadIdx.x;            // 128 threads
    double s1 = g_acc[0 * BS + b];
    double s2 = g_acc[1 * BS + b];
    double s3 = g_acc[2 * BS + b];
    double s4 = g_acc[3 * BS + b];
    double s5 = g_acc[4 * BS + b];
    double c  = s1 / s2;
    double r  = s3 - 2.0 * c * s4 + c * c * s5;
    __shared__ double sh[128];
    sh[b] = r;
    __syncthreads();
    for (int s = 64; s > 0; s >>= 1) {
        if (b < s) sh[b] += sh[b + s];
        __syncthreads();
    }
    if (b == 0) out[0] = (float)(sh[0] / (double)BS);
}

extern "C" void kernel_launch(void* const* d_in, const int* in_sizes, int n_in,
                              void* d_out, int out_size) {
    const float* yp   = (const float*)d_in[0];
    const float* yt   = (const float*)d_in[1];
    const float* vals = (const float*)d_in[2];
    const int*   rows = (const int*)d_in[3];
    const int*   cols = (const int*)d_in[4];
    float*       out  = (float*)d_out;

    zero_acc_kernel<<<1, 5 * BS>>>();
    for (int c = 0; c < NCHUNK; c++) {
        int b0 = c * CH;
        prep_chunk<<<NN / 32, dim3(32, 8)>>>(yp, b0);
        scatter_chunk<<<2368, 256>>>(vals, rows, cols);
        reduce_chunk<<<NN / 256, 256>>>(yt, b0);
    }
    final_kernel<<<1, BS>>>(out);
}